// round 16
// baseline (speedup 1.0000x reference)
#include <cuda_runtime.h>
#include <cstdint>

#define N_PTS   131072
#define C_DIM   64
#define K_CB    512
#define NQ      4
#define HW_SZ   16384
#define P_BLK   32
#define NTHR    512
#define NBLK    (N_PTS / P_BLK)
#define WLCAP   512
#define IDX_OFF 8388608
#define LOSS_OFF 8912896

typedef unsigned long long ull;

// Scratch (allocation-free rule: __device__ globals)
__device__ float    g_G[K_CB * K_CB];    // NEGATED Gram -cb@cb.T (fast path)
__device__ float    g_h[K_CB];           // NEGATED half-norms -0.5||c||^2
__device__ float    g_csq[K_CB];         // ||c||^2, XLA-CPU vectorized-reduce order
__device__ float    g_cbT[C_DIM * K_CB]; // transposed codebook [c][k]
__device__ double   g_loss[NQ];
__device__ unsigned g_done = 0;

// Packed fp32x2 ops (sm_10x). Per-lane rn rounding == scalar fmaf/fadd.
__device__ __forceinline__ ull fma2(ull a, ull b, ull c) {
    ull d;
    asm("fma.rn.f32x2 %0, %1, %2, %3;" : "=l"(d) : "l"(a), "l"(b), "l"(c));
    return d;
}
__device__ __forceinline__ ull add2(ull a, ull b) {
    ull d;
    asm("add.rn.f32x2 %0, %1, %2;" : "=l"(d) : "l"(a), "l"(b));
    return d;
}
__device__ __forceinline__ ull pack2(float lo, float hi) {
    ull d;
    asm("mov.b64 %0, {%1, %2};" : "=l"(d) : "f"(lo), "f"(hi));
    return d;
}
__device__ __forceinline__ void unpack2(float& lo, float& hi, ull v) {
    asm("mov.b64 {%0, %1}, %2;" : "=f"(lo), "=f"(hi) : "l"(v));
}

// ---------------------------------------------------------------------------
// Precompute (negated) G, (negated) h, csq, cbT; zero loss accumulators.
// ---------------------------------------------------------------------------
__global__ void prep_kernel(const float* __restrict__ cb) {
    __shared__ float ci[C_DIM];
    const int i = blockIdx.x;
    const int t = threadIdx.x;
    if (t < C_DIM) ci[t] = cb[i * C_DIM + t];
    __syncthreads();
    {
        const float4* row = (const float4*)(cb + t * C_DIM);
        float s = 0.f;
#pragma unroll
        for (int c4 = 0; c4 < 16; c4++) {
            float4 v = row[c4];
            s = fmaf(ci[4 * c4 + 0], v.x, s);
            s = fmaf(ci[4 * c4 + 1], v.y, s);
            s = fmaf(ci[4 * c4 + 2], v.z, s);
            s = fmaf(ci[4 * c4 + 3], v.w, s);
        }
        g_G[i * K_CB + t] = -s;                 // negated for packed-add subtract
        if (t == i) g_h[i] = -0.5f * s;         // negated half-norm
    }
    if (t < C_DIM) g_cbT[t * K_CB + i] = ci[t]; // transposed copy
    if (t == 0) {
        // csq exactly as XLA:CPU vectorized reduce (NEON width 4):
        // 4 strided lane accumulators, strict per-op rounding (mul+add,
        // no FMA), shuffle-halving horizontal sum: (L0+L2)+(L1+L3).
        float l0 = 0.f, l1 = 0.f, l2 = 0.f, l3 = 0.f;
        for (int j = 0; j < 16; j++) {
            float v0 = ci[4 * j + 0], v1 = ci[4 * j + 1];
            float v2 = ci[4 * j + 2], v3 = ci[4 * j + 3];
            l0 = __fadd_rn(l0, __fmul_rn(v0, v0));
            l1 = __fadd_rn(l1, __fmul_rn(v1, v1));
            l2 = __fadd_rn(l2, __fmul_rn(v2, v2));
            l3 = __fadd_rn(l3, __fmul_rn(v3, v3));
        }
        g_csq[i] = __fadd_rn(__fadd_rn(l0, l2), __fadd_rn(l1, l3));
    }
    if (i == 0 && t < NQ) g_loss[t] = 0.0;
}

// Orderable-float packing: larger float -> larger uint (monotone).
__device__ __forceinline__ unsigned ford(float f) {
    unsigned u = __float_as_uint(f);
    return (u & 0x80000000u) ? ~u : (u | 0x80000000u);
}
__device__ __forceinline__ float funord(unsigned s) {
    unsigned u = (s & 0x80000000u) ? (s ^ 0x80000000u) : ~s;
    return __uint_as_float(u);
}

// ---------------------------------------------------------------------------
// Main fused RVQ kernel. Block = 32 points x 512 codewords, 512 threads,
// 2 blocks/SM. Thread tile: 8 points (pg=tid&3, pairs packed) x 4 k's
// (kg=tid>>2) -> acc2[4][4] = 32 regs. Codebook streamed from L2 once per
// 32 points (half the R15 traffic); 3 syncthreads per stage.
// ---------------------------------------------------------------------------
__global__ __launch_bounds__(NTHR, 2)
void rvq_kernel(const float* __restrict__ x, const float* __restrict__ cb,
                float* __restrict__ out) {
    __shared__ __align__(16) float rs[C_DIM][P_BLK];   // residual [c][p] (8KB)
    __shared__ __align__(16) float rs_t[P_BLK][68];    // residual [p][c] (8.5KB)
    __shared__ unsigned red1[2][P_BLK];         // fast max per point, dbl-buf
    __shared__ ull redmin[2][P_BLK];            // packed (dist,k), dbl-buf
    __shared__ int    idxs[NQ][P_BLK];
    __shared__ double sloss[NQ];
    __shared__ int    wl[WLCAP];                // candidate worklist (p<<9|k)
    __shared__ int    wl_n;

    const int tid   = threadIdx.x;
    const int lane  = tid & 31;
    const int pg    = tid & 3;                  // 0..3, 8 points each
    const int kg    = tid >> 2;                 // 0..127
    const int kbase = kg * 4;
    const int n0    = blockIdx.x * P_BLK;
    const int b     = n0 / HW_SZ;               // 32 | HW, block never crosses b
    const int hw0   = n0 % HW_SZ;
    const float* xbase = x + (size_t)b * C_DIM * HW_SZ + hw0;

    if (tid < P_BLK) {
        red1[0][tid] = 0u;    red1[1][tid] = 0u;
        redmin[0][tid] = ~0ull; redmin[1][tid] = ~0ull;
    }
    if (tid < NQ) sloss[tid] = 0.0;
    if (tid == 0) wl_n = 0;

    const int p_e  = tid & 31;       // elementwise-phase point
    const int cg_e = tid >> 5;       // elementwise-phase channel group (0..15)

    // ---- load x tile (coalesced 128B over p); fill BOTH residual layouts ----
    {
        float v0 = xbase[(size_t)(cg_e * 4 + 0) * HW_SZ + p_e];
        float v1 = xbase[(size_t)(cg_e * 4 + 1) * HW_SZ + p_e];
        float v2 = xbase[(size_t)(cg_e * 4 + 2) * HW_SZ + p_e];
        float v3 = xbase[(size_t)(cg_e * 4 + 3) * HW_SZ + p_e];
        rs[cg_e * 4 + 0][p_e] = v0;
        rs[cg_e * 4 + 1][p_e] = v1;
        rs[cg_e * 4 + 2][p_e] = v2;
        rs[cg_e * 4 + 3][p_e] = v3;
        *((float4*)&rs_t[p_e][cg_e * 4]) = make_float4(v0, v1, v2, v3);
    }

    // ---- acc init: packed (-0.5||c_k||^2), same value both point-halves ----
    ull acc2[4][4];
    {
        float4 hv = *((const float4*)(g_h + kbase));
        ull h0 = pack2(hv.x, hv.x), h1 = pack2(hv.y, hv.y);
        ull h2 = pack2(hv.z, hv.z), h3 = pack2(hv.w, hv.w);
#pragma unroll
        for (int i = 0; i < 4; i++) {
            acc2[i][0] = h0; acc2[i][1] = h1;
            acc2[i][2] = h2; acc2[i][3] = h3;
        }
    }
    __syncthreads();

    // ---- barrier-free matmul, depth-2 cv prefetch ----
    // Per (p,k) cell: one fma.rn per ascending c — byte-identical chain.
#define FMA_BLOCK(CC, CV)                                                  \
    do {                                                                   \
        ulonglong2 xa = *((const ulonglong2*)&rs[(CC)][pg * 8]);           \
        ulonglong2 xb = *((const ulonglong2*)&rs[(CC)][pg * 8 + 4]);       \
        ull c0 = pack2((CV).x, (CV).x), c1 = pack2((CV).y, (CV).y);        \
        ull c2 = pack2((CV).z, (CV).z), c3 = pack2((CV).w, (CV).w);        \
        acc2[0][0] = fma2(xa.x, c0, acc2[0][0]);                           \
        acc2[0][1] = fma2(xa.x, c1, acc2[0][1]);                           \
        acc2[0][2] = fma2(xa.x, c2, acc2[0][2]);                           \
        acc2[0][3] = fma2(xa.x, c3, acc2[0][3]);                           \
        acc2[1][0] = fma2(xa.y, c0, acc2[1][0]);                           \
        acc2[1][1] = fma2(xa.y, c1, acc2[1][1]);                           \
        acc2[1][2] = fma2(xa.y, c2, acc2[1][2]);                           \
        acc2[1][3] = fma2(xa.y, c3, acc2[1][3]);                           \
        acc2[2][0] = fma2(xb.x, c0, acc2[2][0]);                           \
        acc2[2][1] = fma2(xb.x, c1, acc2[2][1]);                           \
        acc2[2][2] = fma2(xb.x, c2, acc2[2][2]);                           \
        acc2[2][3] = fma2(xb.x, c3, acc2[2][3]);                           \
        acc2[3][0] = fma2(xb.y, c0, acc2[3][0]);                           \
        acc2[3][1] = fma2(xb.y, c1, acc2[3][1]);                           \
        acc2[3][2] = fma2(xb.y, c2, acc2[3][2]);                           \
        acc2[3][3] = fma2(xb.y, c3, acc2[3][3]);                           \
    } while (0)
    {
        const float4* cvp = (const float4*)(g_cbT + kbase);
        float4 cvA = __ldg(cvp);
#pragma unroll 2
        for (int c = 0; c < C_DIM - 1; c++) {
            float4 cvN = __ldg(cvp + (size_t)(c + 1) * (K_CB / 4));
            FMA_BLOCK(c, cvA);
            cvA = cvN;
        }
        FMA_BLOCK(C_DIM - 1, cvA);
    }

    // ---- A0: warp maxes of initial scores -> red1[0] (global window) ----
#pragma unroll
    for (int i = 0; i < 4; i++) {
        float l0, h0, l1, h1, l2, h2, l3, h3;
        unpack2(l0, h0, acc2[i][0]);
        unpack2(l1, h1, acc2[i][1]);
        unpack2(l2, h2, acc2[i][2]);
        unpack2(l3, h3, acc2[i][3]);
        float blo = fmaxf(fmaxf(l0, l1), fmaxf(l2, l3));
        float bhi = fmaxf(fmaxf(h0, h1), fmaxf(h2, h3));
        blo = fmaxf(blo, __shfl_xor_sync(0xffffffffu, blo, 4));
        blo = fmaxf(blo, __shfl_xor_sync(0xffffffffu, blo, 8));
        blo = fmaxf(blo, __shfl_xor_sync(0xffffffffu, blo, 16));
        bhi = fmaxf(bhi, __shfl_xor_sync(0xffffffffu, bhi, 4));
        bhi = fmaxf(bhi, __shfl_xor_sync(0xffffffffu, bhi, 8));
        bhi = fmaxf(bhi, __shfl_xor_sync(0xffffffffu, bhi, 16));
        if (lane < 4) {
            atomicMax(&red1[0][pg * 8 + 2 * i + 0], ford(blo));
            atomicMax(&red1[0][pg * 8 + 2 * i + 1], ford(bhi));
        }
    }
    __syncthreads();

    float qsum[4];                   // quantized accumulator (4 channels of p_e)
#pragma unroll
    for (int ii = 0; ii < 4; ii++) qsum[ii] = 0.f;

    // ---- 4 quantizer stages, 3 syncs each ----
#pragma unroll
    for (int q = 0; q < NQ; q++) {
        const int buf = q & 1;

        // P1: push windowed candidates (global window from red1[buf]);
        //     reset the OTHER buffers (unread since q-1's P3 closing sync).
        if (tid < P_BLK) {
            red1[buf ^ 1][tid] = 0u;
            redmin[buf ^ 1][tid] = ~0ull;
        }
#pragma unroll
        for (int i = 0; i < 4; i++) {
            const int pLo = pg * 8 + 2 * i, pHi = pLo + 1;
            const float thrLo = funord(red1[buf][pLo]) - 0.01f;
            const float thrHi = funord(red1[buf][pHi]) - 0.01f;
            float alo[4], ahi[4];
            unpack2(alo[0], ahi[0], acc2[i][0]);
            unpack2(alo[1], ahi[1], acc2[i][1]);
            unpack2(alo[2], ahi[2], acc2[i][2]);
            unpack2(alo[3], ahi[3], acc2[i][3]);
#pragma unroll
            for (int j = 0; j < 4; j++) {
                if (alo[j] >= thrLo) {
                    int pos = atomicAdd(&wl_n, 1);
                    if (pos < WLCAP) wl[pos] = (pLo << 9) | (kbase + j);
                }
                if (ahi[j] >= thrHi) {
                    int pos = atomicAdd(&wl_n, 1);
                    if (pos < WLCAP) wl[pos] = (pHi << 9) | (kbase + j);
                }
            }
        }
        __syncthreads();

        // P2: exact (reference-order) dist per candidate, one thread each.
        {
            const int wn = (wl_n < WLCAP) ? wl_n : WLCAP;
            for (int t = tid; t < wn; t += NTHR) {
                const int e = wl[t];
                const int p = e >> 9;
                const int k = e & 511;
                const float4* c4 = (const float4*)(cb + k * C_DIM);
                const float4* r4 = (const float4*)&rs_t[p][0];
                float dot = 0.f;
#pragma unroll 4
                for (int g = 0; g < 16; g++) {           // ascending-c seq FMA
                    float4 v = c4[g];                     // (Eigen gebp order)
                    float4 r = r4[g];
                    dot = fmaf(r.x, v.x, dot);
                    dot = fmaf(r.y, v.y, dot);
                    dot = fmaf(r.z, v.z, dot);
                    dot = fmaf(r.w, v.w, dot);
                }
                float dist = __fsub_rn(g_csq[k], __fmul_rn(2.0f, dot));
                ull pk = ((ull)ford(dist) << 32) | (unsigned)k;
                atomicMin(&redmin[buf][p], pk);          // min dist, then min k
            }
        }
        __syncthreads();

        // P3: exact elementwise update + cascade + next-stage maxes.
        {
            const int k = (int)(unsigned)(redmin[buf][p_e] & 0xffffffffull);
            const float4 cw = *((const float4*)(cb + (size_t)k * C_DIM + cg_e * 4));
            const float cvv[4] = {cw.x, cw.y, cw.z, cw.w};
            float nr[4];
            double ls = 0.0;
#pragma unroll
            for (int ii = 0; ii < 4; ii++) {
                const int c = cg_e * 4 + ii;
                const float cv = cvv[ii];
                const float r  = rs[c][p_e];
                const float d  = __fsub_rn(cv, r);          // quant - residual
                const float qst = __fadd_rn(r, d);          // straight-through
                qsum[ii] = __fadd_rn(qsum[ii], qst);        // quant_out += qst
                nr[ii] = __fsub_rn(r, cv);                  // residual -= quant
                rs[c][p_e] = nr[ii];
                ls += (double)__fmul_rn(d, d);
            }
            *((float4*)&rs_t[p_e][cg_e * 4]) =
                make_float4(nr[0], nr[1], nr[2], nr[3]);
#pragma unroll
            for (int o = 16; o; o >>= 1)
                ls += __shfl_xor_sync(0xffffffffu, ls, o);
            if (lane == 0) atomicAdd(&sloss[q], ls);
        }
        if (tid < P_BLK)
            idxs[q][tid] = (int)(unsigned)(redmin[buf][tid] & 0xffffffffull);

        if (q < NQ - 1) {
            // cascade: acc += (-G[idx]) slices; then next stage's warp maxes
#pragma unroll
            for (int i = 0; i < 4; i++) {
                const int pA = pg * 8 + 2 * i;
                const int rA = (int)(unsigned)(redmin[buf][pA] & 0xffffffffull);
                const int rB = (int)(unsigned)(redmin[buf][pA + 1] & 0xffffffffull);
                float4 gl = *((const float4*)(g_G + (size_t)rA * K_CB + kbase));
                float4 gh = *((const float4*)(g_G + (size_t)rB * K_CB + kbase));
                acc2[i][0] = add2(acc2[i][0], pack2(gl.x, gh.x));
                acc2[i][1] = add2(acc2[i][1], pack2(gl.y, gh.y));
                acc2[i][2] = add2(acc2[i][2], pack2(gl.z, gh.z));
                acc2[i][3] = add2(acc2[i][3], pack2(gl.w, gh.w));
                // next-stage max for this point pair
                float l0, h0, l1, h1, l2, h2, l3, h3;
                unpack2(l0, h0, acc2[i][0]);
                unpack2(l1, h1, acc2[i][1]);
                unpack2(l2, h2, acc2[i][2]);
                unpack2(l3, h3, acc2[i][3]);
                float blo = fmaxf(fmaxf(l0, l1), fmaxf(l2, l3));
                float bhi = fmaxf(fmaxf(h0, h1), fmaxf(h2, h3));
                blo = fmaxf(blo, __shfl_xor_sync(0xffffffffu, blo, 4));
                blo = fmaxf(blo, __shfl_xor_sync(0xffffffffu, blo, 8));
                blo = fmaxf(blo, __shfl_xor_sync(0xffffffffu, blo, 16));
                bhi = fmaxf(bhi, __shfl_xor_sync(0xffffffffu, bhi, 4));
                bhi = fmaxf(bhi, __shfl_xor_sync(0xffffffffu, bhi, 8));
                bhi = fmaxf(bhi, __shfl_xor_sync(0xffffffffu, bhi, 16));
                if (lane < 4) {
                    atomicMax(&red1[buf ^ 1][pA], ford(blo));
                    atomicMax(&red1[buf ^ 1][pA + 1], ford(bhi));
                }
            }
        }
        if (tid == 0) wl_n = 0;
        __syncthreads();
    }

    // ---- outputs ----
    // indices as float, coalesced: 128 threads cover 32 points x 4 stages
    if (tid < P_BLK * NQ) {
        const int q = tid & 3, p = tid >> 2;
        out[IDX_OFF + (size_t)(n0 + p) * NQ + q] = (float)idxs[q][p];
    }
    // quantized in [B,C,H,W] layout (coalesced 128B over p)
    {
        float* obase = out + (size_t)b * C_DIM * HW_SZ + hw0 + p_e;
#pragma unroll
        for (int ii = 0; ii < 4; ii++) {
            const int c = cg_e * 4 + ii;
            obase[(size_t)c * HW_SZ] = qsum[ii];
        }
    }
    // commit losses: 4 global atomics per block, last block writes output
    if (tid < NQ) atomicAdd(&g_loss[tid], sloss[tid]);
    __syncthreads();
    if (tid == 0) {
        __threadfence();
        unsigned t = atomicAdd(&g_done, 1u);
        if (t == (unsigned)(gridDim.x - 1)) {
            __threadfence();
            g_done = 0;                        // reset for next launch/replay
#pragma unroll
            for (int qq = 0; qq < NQ; qq++)
                out[LOSS_OFF + qq] =
                    (float)(g_loss[qq] * (1.0 / (131072.0 * 64.0)));
        }
    }
}

extern "C" void kernel_launch(void* const* d_in, const int* in_sizes, int n_in,
                              void* d_out, int out_size) {
    (void)in_sizes; (void)n_in; (void)out_size;
    const float* x  = (const float*)d_in[0];
    const float* cb = (const float*)d_in[1];
    float* out = (float*)d_out;

    prep_kernel<<<K_CB, NTHR>>>(cb);
    rvq_kernel<<<NBLK, NTHR>>>(x, cb, out);
}